// round 13
// baseline (speedup 1.0000x reference)
#include <cuda_runtime.h>
#include <cuda_bf16.h>
#include <cstdint>

#define P       4096
#define MDIM    64
#define NB      72           // padded N: 64 features + count col + pad (ldmatrix stride 144B)
#define NJ      16           // K-splits
#define KC      (P / NJ)     // 256 K per CTA
#define MTILE   128          // rows per CTA (4 warps x 32)
#define THREADS 128

#define BROW    144          // SMEM/global B row stride bytes (72 bf16)
#define SM_PLANE (KC * BROW) // 36864 B per plane in SMEM
#define SM_TOTAL (2 * SM_PLANE)

// ---- scratch (allocation-free) ----
__device__ float g_acc[P][NB];                 // accumulated sums + counts (1.2 MB)
__device__ int   g_any;
__device__ __nv_bfloat16 g_B[2][4096][NB];     // hi/lo: hidden^T padded

// ---- helpers ----
__device__ __forceinline__ uint32_t smem_u32(const void* p) {
    uint32_t a;
    asm("{ .reg .u64 t; cvta.to.shared.u64 t, %1; cvt.u32.u64 %0, t; }" : "=r"(a) : "l"(p));
    return a;
}
__device__ __forceinline__ uint32_t pack01(int x, int y) {
    return (x > 0 ? 0x3F80u : 0u) | (y > 0 ? 0x3F800000u : 0u);
}
__device__ __forceinline__ void ldsm_x2_t(uint32_t& r0, uint32_t& r1, uint32_t addr) {
    asm volatile("ldmatrix.sync.aligned.m8n8.x2.trans.shared.b16 {%0,%1}, [%2];"
                 : "=r"(r0), "=r"(r1) : "r"(addr));
}
__device__ __forceinline__ void mma16816(float* d, const uint32_t* a, uint32_t b0, uint32_t b1) {
    asm volatile("mma.sync.aligned.m16n8k16.row.col.f32.bf16.bf16.f32 "
                 "{%0,%1,%2,%3}, {%4,%5,%6,%7}, {%8,%9}, {%0,%1,%2,%3};"
                 : "+f"(d[0]), "+f"(d[1]), "+f"(d[2]), "+f"(d[3])
                 : "r"(a[0]), "r"(a[1]), "r"(a[2]), "r"(a[3]), "r"(b0), "r"(b1));
}

// ---------------------------------------------------------------------------
// prep: hidden [4096][64] f32 -> g_B hi/lo [4096][72] bf16 (exact split).
// col 64 = ones (hi) / zeros (lo) -> GEMM emits neighbor counts.
// Also zeroes g_acc and g_any (stream order protects mma's atomics).
// Index space: (k, quad) with 18 quads of 4 cols per k-row. 288 blocks x 256.
// ---------------------------------------------------------------------------
__global__ void prep_kernel(const float* __restrict__ hidden) {
    int qid = blockIdx.x * blockDim.x + threadIdx.x;     // 0 .. 4096*18-1
    int k = qid / 18, q = qid - k * 18;

    float4 v;
    if (q < 16)      v = ((const float4*)hidden)[k * 16 + q];
    else if (q == 16) v = make_float4(1.0f, 0.0f, 0.0f, 0.0f);
    else              v = make_float4(0.0f, 0.0f, 0.0f, 0.0f);

    __nv_bfloat16 h0 = __float2bfloat16(v.x), h1 = __float2bfloat16(v.y);
    __nv_bfloat16 h2 = __float2bfloat16(v.z), h3 = __float2bfloat16(v.w);
    __nv_bfloat162 hi01 = make_bfloat162(h0, h1), hi23 = make_bfloat162(h2, h3);
    __nv_bfloat162 lo01 = make_bfloat162(__float2bfloat16(v.x - __bfloat162float(h0)),
                                         __float2bfloat16(v.y - __bfloat162float(h1)));
    __nv_bfloat162 lo23 = make_bfloat162(__float2bfloat16(v.z - __bfloat162float(h2)),
                                         __float2bfloat16(v.w - __bfloat162float(h3)));

    *(uint2*)&g_B[0][k][q * 4] = make_uint2(*(uint32_t*)&hi01, *(uint32_t*)&hi23);
    *(uint2*)&g_B[1][k][q * 4] = make_uint2(*(uint32_t*)&lo01, *(uint32_t*)&lo23);
    *(float4*)&g_acc[k][q * 4] = make_float4(0.f, 0.f, 0.f, 0.f);
    if (qid == 0) g_any = 0;
}

// ---------------------------------------------------------------------------
// mma_kernel: grid (32 M-tiles, 16 K-splits), 128 threads, 4 warps x 32 rows.
// Each warp owns two 16-row A fragment sets -> every B ldmatrix feeds 2 mmas.
// ---------------------------------------------------------------------------
__global__ void __launch_bounds__(THREADS, 3)
mma_kernel(const int* __restrict__ nei) {
    extern __shared__ char smem[];
    const uint32_t sb = smem_u32(smem);

    const int tid  = threadIdx.x;
    const int wid  = tid >> 5;
    const int lane = tid & 31;
    const int g    = lane >> 2;      // fragment row group 0..7
    const int tq   = lane & 3;       // fragment k group 0..3

    const int i0 = blockIdx.x * MTILE;
    const int ks = blockIdx.y;
    const int k0 = ks * KC;

    // --- stage B hi/lo slice [KC][72] into SMEM ---
    {
        const uint4* s0 = (const uint4*)&g_B[0][k0][0];
        const uint4* s1 = (const uint4*)&g_B[1][k0][0];
        uint4* d0 = (uint4*)smem;
        uint4* d1 = (uint4*)(smem + SM_PLANE);
#pragma unroll
        for (int it = 0; it < SM_PLANE / 16 / THREADS; it++) {
            int idx = tid + it * THREADS;
            d0[idx] = s0[idx];
            d1[idx] = s1[idx];
        }
    }
    __syncthreads();

    const int row = i0 + wid * 32 + g;   // lane's rows: row, +8, +16, +24

    float d0a[9][4], d1a[9][4];
#pragma unroll
    for (int nf = 0; nf < 9; nf++)
#pragma unroll
        for (int c = 0; c < 4; c++) { d0a[nf][c] = 0.0f; d1a[nf][c] = 0.0f; }

    const int* pa0 = nei + (size_t)row * P + k0 + tq * 2;
    const size_t P8 = (size_t)8 * P, P16 = (size_t)16 * P, P24 = (size_t)24 * P;

    // prologue: A loads for t=0
    int2 w0 = *(const int2*)(pa0);
    int2 w1 = *(const int2*)(pa0 + P8);
    int2 w2 = *(const int2*)(pa0 + 8);
    int2 w3 = *(const int2*)(pa0 + P8 + 8);
    int2 w4 = *(const int2*)(pa0 + P16);
    int2 w5 = *(const int2*)(pa0 + P24);
    int2 w6 = *(const int2*)(pa0 + P16 + 8);
    int2 w7 = *(const int2*)(pa0 + P24 + 8);

#pragma unroll 1
    for (int t = 0; t < KC / 16; t++) {
        uint32_t a0[4], a1[4];
        a0[0] = pack01(w0.x, w0.y);
        a0[1] = pack01(w1.x, w1.y);
        a0[2] = pack01(w2.x, w2.y);
        a0[3] = pack01(w3.x, w3.y);
        a1[0] = pack01(w4.x, w4.y);
        a1[1] = pack01(w5.x, w5.y);
        a1[2] = pack01(w6.x, w6.y);
        a1[3] = pack01(w7.x, w7.y);

        // prefetch A for t+1 (overlaps with ldsm+mma below)
        if (t + 1 < KC / 16) {
            const int* pa = pa0 + (t + 1) * 16;
            w0 = *(const int2*)(pa);
            w1 = *(const int2*)(pa + P8);
            w2 = *(const int2*)(pa + 8);
            w3 = *(const int2*)(pa + P8 + 8);
            w4 = *(const int2*)(pa + P16);
            w5 = *(const int2*)(pa + P24);
            w6 = *(const int2*)(pa + P16 + 8);
            w7 = *(const int2*)(pa + P24 + 8);
        }

        const uint32_t lrow = sb + (t * 16 + (lane & 15)) * BROW;
#pragma unroll
        for (int nf = 0; nf < 9; nf++) {
            uint32_t b0, b1;
            ldsm_x2_t(b0, b1, lrow + nf * 16);
            mma16816(d0a[nf], a0, b0, b1);
            mma16816(d1a[nf], a1, b0, b1);
        }
#pragma unroll
        for (int nf = 0; nf < 8; nf++) {
            uint32_t b0, b1;
            ldsm_x2_t(b0, b1, lrow + SM_PLANE + nf * 16);
            mma16816(d0a[nf], a0, b0, b1);
            mma16816(d1a[nf], a1, b0, b1);
        }
    }

    // --- any-neighbor flag from count column (col 64 = nf 8, tq 0) ---
    {
        bool has = (tq == 0) && (d0a[8][0] > 0.5f || d0a[8][2] > 0.5f ||
                                 d1a[8][0] > 0.5f || d1a[8][2] > 0.5f);
        unsigned b = __ballot_sync(0xffffffffu, has);
        if (lane == 0 && b) atomicOr(&g_any, 1);
    }

    // --- split-K reduce into g_acc via red.global.add ---
    float* gp0 = &g_acc[row][tq * 2];
    float* gp1 = &g_acc[row + 8][tq * 2];
    float* gp2 = &g_acc[row + 16][tq * 2];
    float* gp3 = &g_acc[row + 24][tq * 2];
#pragma unroll
    for (int nf = 0; nf < 9; nf++) {
        atomicAdd(gp0 + nf * 8,     d0a[nf][0]);
        atomicAdd(gp0 + nf * 8 + 1, d0a[nf][1]);
        atomicAdd(gp1 + nf * 8,     d0a[nf][2]);
        atomicAdd(gp1 + nf * 8 + 1, d0a[nf][3]);
        atomicAdd(gp2 + nf * 8,     d1a[nf][0]);
        atomicAdd(gp2 + nf * 8 + 1, d1a[nf][1]);
        atomicAdd(gp3 + nf * 8,     d1a[nf][2]);
        atomicAdd(gp3 + nf * 8 + 1, d1a[nf][3]);
    }
}

// ---------------------------------------------------------------------------
__global__ void finalize_kernel(const float* __restrict__ hidden,
                                float* __restrict__ out) {
    int gidx = blockIdx.x * blockDim.x + threadIdx.x;   // 0 .. P*32-1
    int i = gidx >> 5, c2 = gidx & 31;
    float2 s  = *(const float2*)&g_acc[i][c2 * 2];
    float kf = g_acc[i][MDIM];
    float denom = kf + (4096.0f - kf) * expf(-1.000001f);
    float cs = 1.0f / denom;
    float2 hv = ((const float2*)hidden)[gidx];
    float2 r;
    r.x = (g_any > 0) ? (cs * s.x) : hv.x;
    r.y = (g_any > 0) ? (cs * s.y) : hv.y;
    ((float2*)out)[gidx] = r;
}

// ---------------------------------------------------------------------------
extern "C" void kernel_launch(void* const* d_in, const int* in_sizes, int n_in,
                              void* d_out, int out_size) {
    const float* hidden = nullptr;
    const int* nei = nullptr;
    for (int i = 0; i < n_in; i++) {
        if (in_sizes[i] == P * MDIM)   hidden = (const float*)d_in[i];
        else if (in_sizes[i] == P * P) nei    = (const int*)d_in[i];
    }
    float* out = (float*)d_out;

    cudaFuncSetAttribute(mma_kernel, cudaFuncAttributeMaxDynamicSharedMemorySize, SM_TOTAL);

    prep_kernel<<<(4096 * 18) / 256, 256>>>(hidden);
    mma_kernel<<<dim3(P / MTILE, NJ), THREADS, SM_TOTAL>>>(nei);
    finalize_kernel<<<(P * 32) / 256, 256>>>(hidden, out);
    (void)out_size;
}